// round 6
// baseline (speedup 1.0000x reference)
#include <cuda_runtime.h>
#include <cstdint>

#define B_   256
#define T_   127
#define K_   128
#define H_   256
#define G4_  1024
#define BT_  (B_ * T_)       // 32512
#define CL_  8
#define MB_  16
#define HS_  32
#define NT_  512

__device__ float g_gx[(size_t)BT_ * G4_];    // [bt][row] x-gates + bias

// ----------------------------- helpers --------------------------------------
__device__ __forceinline__ unsigned smem_u32(const void* p) {
    return (unsigned)__cvta_generic_to_shared(p);
}
__device__ __forceinline__ unsigned mapa_rank(unsigned a, unsigned r) {
    unsigned ra; asm("mapa.shared::cluster.u32 %0, %1, %2;" : "=r"(ra) : "r"(a), "r"(r));
    return ra;
}
__device__ __forceinline__ void cluster_sync() {
    asm volatile("barrier.cluster.arrive.aligned;" ::: "memory");
    asm volatile("barrier.cluster.wait.aligned;" ::: "memory");
}
__device__ __forceinline__ void mbar_init(unsigned a, unsigned cnt) {
    asm volatile("mbarrier.init.shared.b64 [%0], %1;" :: "r"(a), "r"(cnt) : "memory");
}
__device__ __forceinline__ void mbar_expect_tx(unsigned a, unsigned bytes) {
    asm volatile("mbarrier.arrive.expect_tx.shared.b64 _, [%0], %1;"
                 :: "r"(a), "r"(bytes) : "memory");
}
__device__ __forceinline__ void mbar_arrive_remote(unsigned ra) {
    asm volatile("mbarrier.arrive.release.cluster.shared::cluster.b64 _, [%0];"
                 :: "r"(ra) : "memory");
}
__device__ __forceinline__ void st_async_f32(unsigned ra, float v, unsigned rmbar) {
    asm volatile("st.async.shared::cluster.mbarrier::complete_tx::bytes.b32 [%0], %1, [%2];"
                 :: "r"(ra), "r"(__float_as_uint(v)), "r"(rmbar) : "memory");
}
__device__ __forceinline__ void mbar_wait(unsigned a, unsigned parity) {
    unsigned done;
    asm volatile("{\n\t.reg .pred p;\n\t"
                 "mbarrier.try_wait.parity.acquire.cluster.shared::cta.b64 p, [%1], %2;\n\t"
                 "selp.b32 %0, 1, 0, p;\n\t}"
                 : "=r"(done) : "r"(a), "r"(parity) : "memory");
    if (!done) {
        asm volatile("{\n\t.reg .pred P1;\n\t"
                     "W_%=:\n\t"
                     "mbarrier.try_wait.parity.acquire.cluster.shared::cta.b64 P1, [%0], %1, 0x989680;\n\t"
                     "@P1 bra.uni D_%=;\n\t"
                     "bra.uni W_%=;\n\t"
                     "D_%=:\n\t}"
                     :: "r"(a), "r"(parity) : "memory");
    }
}
__device__ __forceinline__ float sigm(float x) { return 1.f / (1.f + __expf(-x)); }
__device__ __forceinline__ float ftanh(float x) { return 2.f / (1.f + __expf(-2.f * x)) - 1.f; }
__device__ __forceinline__ unsigned long long pack2(float v) {
    unsigned long long d; unsigned u = __float_as_uint(v);
    asm("mov.b64 %0, {%1, %1};" : "=l"(d) : "r"(u)); return d;
}
__device__ __forceinline__ void fma2(unsigned long long& a, unsigned long long w,
                                     unsigned long long x) {
    asm("fma.rn.f32x2 %0, %1, %2, %0;" : "+l"(a) : "l"(w), "l"(x));
}
__device__ __forceinline__ float2 unpack2(unsigned long long a) {
    unsigned lo, hi; asm("mov.b64 {%0, %1}, %2;" : "=r"(lo), "=r"(hi) : "l"(a));
    return make_float2(__uint_as_float(lo), __uint_as_float(hi));
}

// ---------------- Kernel A: softmax alpha + weight output (512 thr) ---------
__global__ void __launch_bounds__(512) k_alpha(const float* __restrict__ inp,
                                               const float* __restrict__ fc_w,
                                               float* __restrict__ out_w) {
    __shared__ float wx[128];
    __shared__ float part[4][128];
    __shared__ float redm[4], reds[4];
    const int tid = threadIdx.x, b = blockIdx.x;
    const int k = tid & 127, tq = tid >> 7;
    if (tid < 128) wx[tid] = (tid < T_) ? fc_w[2 * H_ + tid] : 0.f;
    __syncthreads();

    const float* ib = inp + (size_t)b * T_ * K_;
    float acc = 0.f;
    const int t0 = tq * 32, t1 = (t0 + 32 < T_) ? t0 + 32 : T_;
    for (int t = t0; t < t1; t++) acc += ib[t * K_ + k] * wx[t];
    part[tq][k] = acc;
    __syncthreads();

    float a = part[0][k] + part[1][k] + part[2][k] + part[3][k];
    float m = a;
#pragma unroll
    for (int o = 16; o; o >>= 1) m = fmaxf(m, __shfl_xor_sync(~0u, m, o));
    redm[(tid >> 5) & 3] = m;          // duplicate warps write identical values
    __syncthreads();
    m = fmaxf(fmaxf(redm[0], redm[1]), fmaxf(redm[2], redm[3]));
    float e = __expf(a - m), s = e;
#pragma unroll
    for (int o = 16; o; o >>= 1) s += __shfl_xor_sync(~0u, s, o);
    reds[(tid >> 5) & 3] = s;
    __syncthreads();
    s = reds[0] + reds[1] + reds[2] + reds[3];
    const float alpha = e / s;

    float* ob = out_w + (size_t)b * T_ * K_;
    for (int t = tq; t < T_; t += 4) ob[t * K_ + k] = alpha * ib[t * K_ + k];
}

// ---------------- Kernel X: g_gx = xw @ W_ih^T + bias -----------------------
#define XS_STR 68
#define WS_STR 132
#define GX_XS  (128 * XS_STR)
#define GX_WS  (128 * WS_STR)
#define GX_SMEMB ((GX_XS + GX_WS + 128) * 4)

__global__ void __launch_bounds__(NT_, 2) k_xgemm(const float* __restrict__ xw,
                                                  const float* __restrict__ W_ih,
                                                  const float* __restrict__ b_ih,
                                                  const float* __restrict__ b_hh) {
    extern __shared__ float s[];
    float* xs  = s;                    // [k][68]
    float* ws  = s + GX_XS;            // [k][132]
    float* bsm = ws + GX_WS;
    const int tid = threadIdx.x;
    const int mt = blockIdx.x >> 3, rt = blockIdx.x & 7;
    const int bt0 = mt * 64;

#pragma unroll
    for (int it = 0; it < 16; it++) {
        int idx = tid + NT_ * it;
        int k = idx & 127, b = idx >> 7;
        xs[k * XS_STR + b] = xw[(size_t)(bt0 + b) * K_ + k];
    }
#pragma unroll
    for (int it = 0; it < 32; it++) {
        int idx = tid + NT_ * it;
        int k = idx & 127, r = idx >> 7;
        ws[k * WS_STR + r] = W_ih[(rt * 128 + r) * K_ + k];
    }
    if (tid < 128) bsm[tid] = b_ih[rt * 128 + tid] + b_hh[rt * 128 + tid];
    __syncthreads();

    const int r = tid & 127, q = tid >> 7;
    const float* xq = xs + q * 16;
    unsigned long long A[8] = {0, 0, 0, 0, 0, 0, 0, 0};
#pragma unroll 4
    for (int k = 0; k < 128; k++) {
        unsigned long long w2 = pack2(ws[k * WS_STR + r]);
        const ulonglong2* xp = reinterpret_cast<const ulonglong2*>(xq + k * XS_STR);
        ulonglong2 x0 = xp[0], x1 = xp[1], x2 = xp[2], x3 = xp[3];
        fma2(A[0], w2, x0.x); fma2(A[1], w2, x0.y);
        fma2(A[2], w2, x1.x); fma2(A[3], w2, x1.y);
        fma2(A[4], w2, x2.x); fma2(A[5], w2, x2.y);
        fma2(A[6], w2, x3.x); fma2(A[7], w2, x3.y);
    }
    float bias = bsm[r];
    const size_t col = (size_t)rt * 128 + r;
#pragma unroll
    for (int j = 0; j < 8; j++) {
        float2 v = unpack2(A[j]);
        g_gx[(size_t)(bt0 + q * 16 + 2 * j)     * G4_ + col] = v.x + bias;
        g_gx[(size_t)(bt0 + q * 16 + 2 * j + 1) * G4_ + col] = v.y + bias;
    }
}

// ---------------- Kernel L: recurrence, mbarrier/st.async exchange ----------
#define HTSTR   5120                        // floats per h buffer (256*20)
#define GBSTR   4352                        // floats per gates buffer (2*128*17)
#define OFF_WH  0                           // [256 n][128 r]
#define OFF_HT  (OFF_WH + 256 * 128)        // [2][256 n][20 m]
#define OFF_GB  (OFF_HT + 2 * HTSTR)        // [2][2 nh][128 r][17]
#define OFF_BAR (OFF_GB + 2 * GBSTR)        // u64 barriers: full0 full1 empty0 empty1
#define L_SMEMB ((OFF_BAR + 16) * 4)        // ~206912 B

__global__ void __launch_bounds__(NT_, 1) __cluster_dims__(CL_, 1, 1)
k_lstm(const float* __restrict__ W_hh, float* __restrict__ out_h) {
    extern __shared__ float sm[];
    float* Wh = sm + OFF_WH;
    float* hT = sm + OFF_HT;
    float* gb = sm + OFF_GB;

    const int tid = threadIdx.x;
    unsigned rank; asm("mov.u32 %0, %%cluster_ctarank;" : "=r"(rank));
    const int b0 = (blockIdx.x / CL_) * MB_;
    const unsigned barB = smem_u32(sm + OFF_BAR);   // full[2] then empty[2]

    // stage W_hh slice transposed: Wh[n*128 + rl] = W_hh[grow(rl)*H + n]
#pragma unroll
    for (int it = 0; it < 64; it++) {
        int idx = tid + NT_ * it;
        int n = idx & 255, rl = idx >> 8;
        int grow = (rl >> 5) * H_ + (int)rank * HS_ + (rl & 31);
        Wh[n * 128 + rl] = W_hh[grow * H_ + n];
    }
#pragma unroll
    for (int it = 0; it < 20; it++) hT[tid + NT_ * it] = 0.f;   // both buffers

    if (tid == 0) {
        mbar_init(barB + 0, 1);   // full[0]
        mbar_init(barB + 8, 1);   // full[1]
        mbar_init(barB + 16, 8);  // empty[0]
        mbar_init(barB + 24, 8);  // empty[1]
    }

    // gemv roles
    const int r  = tid & 127;
    const int mh = (tid >> 7) & 1;
    const int nh = tid >> 8;
    const int grow_r = (r >> 5) * H_ + (int)rank * HS_ + (r & 31);
    const float* Wp = Wh + nh * (128 * 128) + r;
    float* gbp = gb + nh * (128 * 17) + r * 17 + mh * 8;

    // cell roles + remote addresses
    const int cjl = tid & 31, cm = tid >> 5;
    unsigned hdst[CL_], rfull[CL_], rempty[CL_];
    {
        unsigned la = smem_u32(&hT[((int)rank * HS_ + cjl) * 20 + cm]);
#pragma unroll
        for (unsigned pr = 0; pr < CL_; pr++) {
            hdst[pr]   = mapa_rank(la, pr);
            unsigned rb = mapa_rank(barB, pr);
            rfull[pr]  = rb;            // + (p^1)*8 at use
            rempty[pr] = rb + 16;       // + p*8 at use
        }
    }
    float c_reg = 0.f;
    float* outp = out_h + (size_t)(b0 + cm) * T_ * H_ + (int)rank * HS_ + cjl;

    __syncthreads();
    cluster_sync();                     // barriers + zeroed hT visible cluster-wide

    for (int t = 0; t < T_; t++) {
        const int p = t & 1;
        const unsigned pw = (unsigned)(((t - 1) >> 1) & 1);

        // prefetch x-gates (coalesced LDG, consumed after gemv)
        float gx0, gx1, gx2, gx3;
        {
            const int j0 = mh * 8 + nh * 4;
            const float* gp = g_gx + (size_t)((b0 + j0) * T_ + t) * G4_ + grow_r;
            const size_t st = (size_t)T_ * G4_;
            gx0 = gp[0]; gx1 = gp[st]; gx2 = gp[2 * st]; gx3 = gp[3 * st];
        }

        if (t > 0) mbar_wait(barB + p * 8, pw);     // full[p]: h arrived (acquire)

        // gemv over hT[p]: 128 n, 8 batches
        const float* Hp = hT + p * HTSTR + nh * (128 * 20) + mh * 8;
        unsigned long long A0 = 0, A1 = 0, A2 = 0, A3 = 0;
#pragma unroll 4
        for (int n = 0; n < 128; n++) {
            unsigned long long w2 = pack2(Wp[n * 128]);
            const ulonglong2* hp = reinterpret_cast<const ulonglong2*>(Hp + n * 20);
            ulonglong2 ha = hp[0], hb = hp[1];
            fma2(A0, w2, ha.x); fma2(A1, w2, ha.y);
            fma2(A2, w2, hb.x); fma2(A3, w2, hb.y);
        }
        float2 p0 = unpack2(A0), p1 = unpack2(A1), p2 = unpack2(A2), p3 = unpack2(A3);
        if (nh == 0) { p0.x += gx0; p0.y += gx1; p1.x += gx2; p1.y += gx3; }
        else         { p2.x += gx0; p2.y += gx1; p3.x += gx2; p3.y += gx3; }
        float* gq = gbp + p * GBSTR;
        gq[0] = p0.x; gq[1] = p0.y; gq[2] = p1.x; gq[3] = p1.y;
        gq[4] = p2.x; gq[5] = p2.y; gq[6] = p3.x; gq[7] = p3.y;
        __syncthreads();                 // hT[p] reads done; gb[p] visible

        if (t < T_ - 1 && tid == 0) {    // release our hT[p] to producers
#pragma unroll
            for (int pr = 0; pr < CL_; pr++) mbar_arrive_remote(rempty[pr] + p * 8);
        }

        // cell
        const float* g0 = gb + p * GBSTR;
        const float* g1 = g0 + 128 * 17;
        float gi = g0[cjl * 17 + cm]        + g1[cjl * 17 + cm];
        float gf = g0[(32 + cjl) * 17 + cm] + g1[(32 + cjl) * 17 + cm];
        float gg = g0[(64 + cjl) * 17 + cm] + g1[(64 + cjl) * 17 + cm];
        float go = g0[(96 + cjl) * 17 + cm] + g1[(96 + cjl) * 17 + cm];
        c_reg = sigm(gf) * c_reg + sigm(gi) * ftanh(gg);
        float hn = sigm(go) * ftanh(c_reg);

        *outp = hn; outp += H_;          // coalesced STG

        if (t < T_ - 1) {
            if (tid == 0) mbar_expect_tx(barB + (p ^ 1) * 8, 16384);
            if (t >= 1) mbar_wait(barB + 16 + (p ^ 1) * 8, pw);   // empty[p^1]
            const unsigned hoff = (unsigned)((p ^ 1) * HTSTR * 4);
            const unsigned boff = (unsigned)((p ^ 1) * 8);
#pragma unroll
            for (int pr = 0; pr < CL_; pr++)
                st_async_f32(hdst[pr] + hoff, hn, rfull[pr] + boff);
        }
    }
    cluster_sync();                      // drain async traffic before teardown
}

// ---------------- Launch -----------------------------------------------------
extern "C" void kernel_launch(void* const* d_in, const int* in_sizes, int n_in,
                              void* d_out, int out_size) {
    const float* input = (const float*)d_in[0];
    const float* W_ih  = (const float*)d_in[1];
    const float* W_hh  = (const float*)d_in[2];
    const float* b_ih  = (const float*)d_in[3];
    const float* b_hh  = (const float*)d_in[4];
    const float* fc_w  = (const float*)d_in[5];
    // d_in[6] = fc_b (cancels inside softmax)

    float* out   = (float*)d_out;
    float* out_w = out;                              // (B,T,K)
    float* out_h = out + (size_t)B_ * T_ * K_;       // (B,T,H)

    cudaFuncSetAttribute(k_xgemm, cudaFuncAttributeMaxDynamicSharedMemorySize, GX_SMEMB);
    cudaFuncSetAttribute(k_lstm,  cudaFuncAttributeMaxDynamicSharedMemorySize, L_SMEMB);

    k_alpha<<<B_, 512>>>(input, fc_w, out_w);
    k_xgemm<<<(BT_ / 64) * 8, NT_, GX_SMEMB>>>(out_w, W_ih, b_ih, b_hh);
    k_lstm<<<(B_ / MB_) * CL_, NT_, L_SMEMB>>>(W_hh, out_h);
}